// round 14
// baseline (speedup 1.0000x reference)
#include <cuda_runtime.h>
#include <cuda_fp16.h>
#include <cuda_fp8.h>

// IntDVF: scaling-and-squaring integration of a stationary velocity field.
//   ddf = dvf / 2^7;  repeat 7x: ddf = ddf + warp(ddf, ddf)
// Shapes: (B=2, 128,128,128, 3) float32, trilinear with clamped indices.
//
// R14:
//  - CLAMP-FREE gathers: loc is clamped in FLOAT domain to [0, 127-1ulp].
//    (loc<0: reference returns edge value regardless of weights -> exact.
//     loc>127: error <= 2^-17 * voxel delta, boundary only -> negligible.)
//    j=(int)loc in [0,126], j+1 <= 127 always in bounds: one corner base
//    pointer + 8 immediate offsets; 12 IMNMX + index chains deleted.
//  - Z-PAIR: 2 voxels (z even, z+1) per thread. Self-read LDG.128,
//    lo LDG.64, stores vectorized; decode/pointer math amortized 2x.
//  - carry = hi(half4) + lo(e4m3 uchar4, scaled 2^(18-i)); gathers read hi;
//    half2-packed interpolation (2 HFMA2/corner).

#define DDIM 128
#define DN   (DDIM * DDIM * DDIM)   // 2097152
#define NBATCH 2
#define NVOX (NBATCH * DN)          // 4194304
#define NTHREADS 256
#define PBLOCKS (NVOX / NTHREADS)          // 16384 (pad kernel)
#define NBLOCKS (NVOX / (2 * NTHREADS))    // 8192  (step kernel, 2 vox/thread)

// largest float < 127.0f  (0x42FE0000 - 1)
#define CLAMP_HI __uint_as_float(0x42FDFFFFu)

struct alignas(8)  H4 { __half2 xy; __half2 zw; };
struct alignas(16) H8 { H4 a, b; };

__device__ H4           g_hA[NVOX];
__device__ H4           g_hB[NVOX];
__device__ unsigned int g_loA[NVOX];   // uchar4: e4m3 x,y,z residuals + pad
__device__ unsigned int g_loB[NVOX];

__device__ __forceinline__ H4 pack_h4(float x, float y, float z) {
    H4 h;
    h.xy = __floats2half2_rn(x, y);
    h.zw = __floats2half2_rn(z, 0.0f);
    return h;
}

__device__ __forceinline__ unsigned int pack_lo(float rx, float ry, float rz) {
    __nv_fp8x2_storage_t b01 =
        __nv_cvt_float2_to_fp8x2(make_float2(rx, ry), __NV_SATFINITE, __NV_E4M3);
    __nv_fp8_storage_t b2 =
        __nv_cvt_float_to_fp8(rz, __NV_SATFINITE, __NV_E4M3);
    return (unsigned int)b01 | ((unsigned int)b2 << 16);
}

// dvf (AoS float3) -> scaled hi/lo split into A (1 vox/thread)
__global__ __launch_bounds__(NTHREADS) void k_scale_pad(const float* __restrict__ in,
                                                        float S) {
    const float SC = 1.0f / 128.0f;  // 2^-7
    int t = blockIdx.x * NTHREADS + threadIdx.x;       // t < NVOX always
    const float* p = in + (size_t)t * 3;
    float x = p[0] * SC, y = p[1] * SC, z = p[2] * SC;
    H4 h = pack_h4(x, y, z);
    g_hA[t] = h;
    float2 hxy = __half22float2(h.xy);
    float  hz  = __half2float(__low2half(h.zw));
    g_loA[t] = pack_lo((x - hxy.x) * S, (y - hxy.y) * S, (z - hz) * S);
}

// One step, 2 voxels (z even, z+1) per thread.
template <bool SRC_IS_A, bool PACK>
__global__ __launch_bounds__(NTHREADS) void k_step(float* __restrict__ out3,
                                                   float invS_in, float S_out) {
    const H4*           __restrict__ hsrc  = SRC_IS_A ? g_hA  : g_hB;
    const unsigned int* __restrict__ losrc = SRC_IS_A ? g_loA : g_loB;
    H4*                 __restrict__ hdst  = SRC_IS_A ? g_hB  : g_hA;
    unsigned int*       __restrict__ lodst = SRC_IS_A ? g_loB : g_loA;

    int t0 = (blockIdx.x * NTHREADS + threadIdx.x) * 2;  // even, t0+1 same row
    int b = t0 >> 21;                                    // DN = 2^21
    int v = t0 & (DN - 1);
    int z0 = v & 127;                                    // even
    int y  = (v >> 7) & 127;
    int x  = v >> 14;

    const H4* __restrict__ hb = hsrc + (size_t)b * DN;

    // Vectorized self-reads: two H4 (LDG.128) + two lo words (LDG.64).
    H8    hpair = *reinterpret_cast<const H8*>(hsrc + t0);
    uint2 lpair = *reinterpret_cast<const uint2*>(losrc + t0);

    H4 hout[2];
    unsigned int loout[2];
    float axs[2], ays[2], azs[2];

    #pragma unroll
    for (int p = 0; p < 2; p++) {
        H4 hself = p ? hpair.b : hpair.a;
        unsigned int lw = p ? lpair.y : lpair.x;

        __half2_raw h01r = __nv_cvt_fp8x2_to_halfraw2(
            (__nv_fp8x2_storage_t)(lw & 0xFFFFu), __NV_E4M3);
        __half_raw h2r = __nv_cvt_fp8_to_halfraw(
            (__nv_fp8_storage_t)((lw >> 16) & 0xFFu), __NV_E4M3);
        float2 lo01 = __half22float2(*(__half2*)&h01r);
        float  lo2  = __half2float(*(__half*)&h2r);

        float2 hxy = __half22float2(hself.xy);
        float  hz  = __half2float(__low2half(hself.zw));
        float dx = fmaf(lo01.x, invS_in, hxy.x);
        float dy = fmaf(lo01.y, invS_in, hxy.y);
        float dz = fmaf(lo2,    invS_in, hz);

        // float-domain clamp (exact vs reference; see header comment)
        float lx = fminf(fmaxf((float)x        + dx, 0.0f), CLAMP_HI);
        float ly = fminf(fmaxf((float)y        + dy, 0.0f), CLAMP_HI);
        float lz = fminf(fmaxf((float)(z0 + p) + dz, 0.0f), CLAMP_HI);

        int jx = (int)lx, jy = (int)ly, jz = (int)lz;   // trunc == floor (>=0)
        float wx1 = lx - (float)jx;
        float wy1 = ly - (float)jy;
        float wz1 = lz - (float)jz;
        float wx0 = 1.0f - wx1, wy0 = 1.0f - wy1, wz0 = 1.0f - wz1;

        // single corner base; all 8 offsets are compile-time immediates
        const H4* __restrict__ cp = hb + ((jx << 14) + (jy << 7) + jz);
        H4 c000 = cp[0];
        H4 c001 = cp[1];
        H4 c010 = cp[128];
        H4 c011 = cp[129];
        H4 c100 = cp[16384];
        H4 c101 = cp[16385];
        H4 c110 = cp[16512];
        H4 c111 = cp[16513];

        float w00 = wx0 * wy0;
        float w01 = wx0 * wy1;
        float w10 = wx1 * wy0;
        float w11 = wx1 * wy1;

        float w000 = w00 * wz0, w001 = w00 * wz1;
        float w010 = w01 * wz0, w011 = w01 * wz1;
        float w100 = w10 * wz0, w101 = w10 * wz1;
        float w110 = w11 * wz0, w111 = w11 * wz1;

        __half2 acc_xy = __floats2half2_rn(0.0f, 0.0f);
        __half2 acc_z  = acc_xy;
        #define ACC(W, C) do {                               \
            __half2 _w2 = __floats2half2_rn((W), (W));       \
            acc_xy = __hfma2(_w2, (C).xy, acc_xy);           \
            acc_z  = __hfma2(_w2, (C).zw, acc_z);            \
        } while (0)
        ACC(w000, c000); ACC(w001, c001);
        ACC(w010, c010); ACC(w011, c011);
        ACC(w100, c100); ACC(w101, c101);
        ACC(w110, c110); ACC(w111, c111);
        #undef ACC

        float2 ixy = __half22float2(acc_xy);
        float  izf = __half2float(__low2half(acc_z));
        float ax = dx + ixy.x;
        float ay = dy + ixy.y;
        float az = dz + izf;

        if (PACK) {
            axs[p] = ax; ays[p] = ay; azs[p] = az;
        } else {
            H4 h = pack_h4(ax, ay, az);
            hout[p] = h;
            float2 oxy = __half22float2(h.xy);
            float  oz  = __half2float(__low2half(h.zw));
            loout[p] = pack_lo((ax - oxy.x) * S_out,
                               (ay - oxy.y) * S_out,
                               (az - oz) * S_out);
        }
    }

    if (PACK) {
        // 6 floats, 8B-aligned -> 3 STG.64
        float2* q = reinterpret_cast<float2*>(out3 + (size_t)t0 * 3);
        q[0] = make_float2(axs[0], ays[0]);
        q[1] = make_float2(azs[0], axs[1]);
        q[2] = make_float2(ays[1], azs[1]);
    } else {
        H8 ho; ho.a = hout[0]; ho.b = hout[1];
        *reinterpret_cast<H8*>(hdst + t0) = ho;                       // STG.128
        *reinterpret_cast<uint2*>(lodst + t0) = make_uint2(loout[0], loout[1]);
    }
}

extern "C" void kernel_launch(void* const* d_in, const int* in_sizes, int n_in,
                              void* d_out, int out_size) {
    const float* dvf = (const float*)d_in[0];
    float* out = (float*)d_out;

    // Per-step fp8 residual scales: field magnitude ~2^(i-7) after i steps,
    // residual ~2^-11 of that -> scale 2^(18-i) centers it in e4m3 range.
    float S[8];
    for (int i = 0; i < 8; i++) S[i] = ldexpf(1.0f, 18 - i);

    // ddf0 (i=0) into A.
    k_scale_pad<<<PBLOCKS, NTHREADS>>>(dvf, S[0]);

    // 7 squaring steps, ping-pong A<->B; final step writes float3 to d_out.
    k_step<true,  false><<<NBLOCKS, NTHREADS>>>(nullptr, 1.0f / S[0], S[1]); // A->B
    k_step<false, false><<<NBLOCKS, NTHREADS>>>(nullptr, 1.0f / S[1], S[2]); // B->A
    k_step<true,  false><<<NBLOCKS, NTHREADS>>>(nullptr, 1.0f / S[2], S[3]); // A->B
    k_step<false, false><<<NBLOCKS, NTHREADS>>>(nullptr, 1.0f / S[3], S[4]); // B->A
    k_step<true,  false><<<NBLOCKS, NTHREADS>>>(nullptr, 1.0f / S[4], S[5]); // A->B
    k_step<false, false><<<NBLOCKS, NTHREADS>>>(nullptr, 1.0f / S[5], S[6]); // B->A
    k_step<true,  true ><<<NBLOCKS, NTHREADS>>>(out, 1.0f / S[6], 0.0f);     // A->out
}

// round 15
// speedup vs baseline: 1.1445x; 1.1445x over previous
#include <cuda_runtime.h>
#include <cuda_fp16.h>
#include <cuda_fp8.h>

// IntDVF: scaling-and-squaring integration of a stationary velocity field.
//   ddf = dvf / 2^7;  repeat 7x: ddf = ddf + warp(ddf, ddf)
// Shapes: (B=2, 128,128,128, 3) float32, trilinear with clamped indices.
//
// R15 = R13 (best structure: 1 vox/thread, 256 thr, 16384 blocks, occ 85%)
//       + clamp-free gathers from R14 (the good half of that experiment;
//       R14's z-pair halved the warp pool and went latency-bound: reverted).
//  - loc clamped in FLOAT domain to [0, 127-1ulp]:
//      loc<0: reference's both-corner clamp returns the edge value for any
//             weights -> clamping loc to 0 is exact.
//      loc>127: both corners clamp to 127 -> result is edge value; clamping
//             to 127-1ulp gives the same corners, weight error <= 2^-17.
//    Then j=(int)loc in [0,126], j+1 always in bounds: trunc==floor, one
//    corner base pointer + 8 immediate offsets; all integer clamps deleted.
//  - carry = hi(half4, gather shadow) + lo(e4m3 uchar4, scaled 2^(18-i)).
//  - half2-packed interpolation: 2 HFMA2 per corner.

#define DDIM 128
#define DN   (DDIM * DDIM * DDIM)   // 2097152
#define NBATCH 2
#define NVOX (NBATCH * DN)          // 4194304
#define NTHREADS 256
#define NBLOCKS (NVOX / NTHREADS)   // 16384

// largest float < 127.0f
#define CLAMP_HI __uint_as_float(0x42FDFFFFu)

struct alignas(8) H4 { __half2 xy; __half2 zw; };

__device__ H4           g_hA[NVOX];
__device__ H4           g_hB[NVOX];
__device__ unsigned int g_loA[NVOX];   // uchar4: e4m3 x,y,z residuals + pad
__device__ unsigned int g_loB[NVOX];

__device__ __forceinline__ H4 pack_h4(float x, float y, float z) {
    H4 h;
    h.xy = __floats2half2_rn(x, y);
    h.zw = __floats2half2_rn(z, 0.0f);
    return h;
}

__device__ __forceinline__ unsigned int pack_lo(float rx, float ry, float rz) {
    __nv_fp8x2_storage_t b01 =
        __nv_cvt_float2_to_fp8x2(make_float2(rx, ry), __NV_SATFINITE, __NV_E4M3);
    __nv_fp8_storage_t b2 =
        __nv_cvt_float_to_fp8(rz, __NV_SATFINITE, __NV_E4M3);
    return (unsigned int)b01 | ((unsigned int)b2 << 16);
}

// Write hi + scaled fp8 residual word.
__device__ __forceinline__ void store_split(H4* hp, unsigned int* lop,
                                            int t, float S,
                                            float x, float y, float z) {
    H4 h = pack_h4(x, y, z);
    hp[t] = h;
    float2 hxy = __half22float2(h.xy);
    float  hz  = __half2float(__low2half(h.zw));
    lop[t] = pack_lo((x - hxy.x) * S, (y - hxy.y) * S, (z - hz) * S);
}

// dvf (AoS float3) -> scaled hi/lo split into A
__global__ __launch_bounds__(NTHREADS) void k_scale_pad(const float* __restrict__ in,
                                                        float S) {
    const float SC = 1.0f / 128.0f;  // 2^-7
    int t = blockIdx.x * NTHREADS + threadIdx.x;       // t < NVOX always
    const float* p = in + (size_t)t * 3;
    store_split(g_hA, g_loA, t, S, p[0] * SC, p[1] * SC, p[2] * SC);
}

// One step: dst = src + trilinear(src_hi, grid + src).
template <bool SRC_IS_A, bool PACK>
__global__ __launch_bounds__(NTHREADS) void k_step(float* __restrict__ out3,
                                                   float invS_in, float S_out) {
    const H4*           __restrict__ hsrc  = SRC_IS_A ? g_hA  : g_hB;
    const unsigned int* __restrict__ losrc = SRC_IS_A ? g_loA : g_loB;
    H4*                 __restrict__ hdst  = SRC_IS_A ? g_hB  : g_hA;
    unsigned int*       __restrict__ lodst = SRC_IS_A ? g_loB : g_loA;

    int t = blockIdx.x * NTHREADS + threadIdx.x;       // t < NVOX always
    int b = t >> 21;                                   // DN = 2^21
    int v = t & (DN - 1);
    int z = v & 127;
    int y = (v >> 7) & 127;
    int x = v >> 14;

    const H4* __restrict__ hb = hsrc + (size_t)b * DN;

    // Self-read: carry = hi + lo * invS
    H4 hself = hsrc[t];
    unsigned int lw = losrc[t];
    __half2_raw h01r = __nv_cvt_fp8x2_to_halfraw2(
        (__nv_fp8x2_storage_t)(lw & 0xFFFFu), __NV_E4M3);
    __half_raw h2r = __nv_cvt_fp8_to_halfraw(
        (__nv_fp8_storage_t)((lw >> 16) & 0xFFu), __NV_E4M3);
    float2 lo01 = __half22float2(*(__half2*)&h01r);
    float  lo2  = __half2float(*(__half*)&h2r);

    float2 hxy = __half22float2(hself.xy);
    float  hz  = __half2float(__low2half(hself.zw));
    float dx = fmaf(lo01.x, invS_in, hxy.x);
    float dy = fmaf(lo01.y, invS_in, hxy.y);
    float dz = fmaf(lo2,    invS_in, hz);

    // float-domain clamp (exact vs reference; see header comment)
    float lx = fminf(fmaxf((float)x + dx, 0.0f), CLAMP_HI);
    float ly = fminf(fmaxf((float)y + dy, 0.0f), CLAMP_HI);
    float lz = fminf(fmaxf((float)z + dz, 0.0f), CLAMP_HI);

    int jx = (int)lx, jy = (int)ly, jz = (int)lz;   // trunc == floor (>= 0)
    float wx1 = lx - (float)jx;
    float wy1 = ly - (float)jy;
    float wz1 = lz - (float)jz;
    float wx0 = 1.0f - wx1, wy0 = 1.0f - wy1, wz0 = 1.0f - wz1;

    // single corner base; all 8 offsets are compile-time immediates
    const H4* __restrict__ cp = hb + ((jx << 14) + (jy << 7) + jz);
    H4 c000 = cp[0];
    H4 c001 = cp[1];
    H4 c010 = cp[128];
    H4 c011 = cp[129];
    H4 c100 = cp[16384];
    H4 c101 = cp[16385];
    H4 c110 = cp[16512];
    H4 c111 = cp[16513];

    float w00 = wx0 * wy0;
    float w01 = wx0 * wy1;
    float w10 = wx1 * wy0;
    float w11 = wx1 * wy1;

    float w000 = w00 * wz0, w001 = w00 * wz1;
    float w010 = w01 * wz0, w011 = w01 * wz1;
    float w100 = w10 * wz0, w101 = w10 * wz1;
    float w110 = w11 * wz0, w111 = w11 * wz1;

    // half2-packed accumulation: 2 HFMA2 per corner.
    __half2 acc_xy = __floats2half2_rn(0.0f, 0.0f);
    __half2 acc_z  = acc_xy;
    #define ACC(W, C) do {                                   \
        __half2 _w2 = __floats2half2_rn((W), (W));           \
        acc_xy = __hfma2(_w2, (C).xy, acc_xy);               \
        acc_z  = __hfma2(_w2, (C).zw, acc_z);                \
    } while (0)
    ACC(w000, c000); ACC(w001, c001);
    ACC(w010, c010); ACC(w011, c011);
    ACC(w100, c100); ACC(w101, c101);
    ACC(w110, c110); ACC(w111, c111);
    #undef ACC

    float2 ixy = __half22float2(acc_xy);
    float  izf = __half2float(__low2half(acc_z));
    float ax = dx + ixy.x;
    float ay = dy + ixy.y;
    float az = dz + izf;

    if (PACK) {
        float* q = out3 + (size_t)t * 3;
        q[0] = ax; q[1] = ay; q[2] = az;
    } else {
        store_split(hdst, lodst, t, S_out, ax, ay, az);
    }
}

extern "C" void kernel_launch(void* const* d_in, const int* in_sizes, int n_in,
                              void* d_out, int out_size) {
    const float* dvf = (const float*)d_in[0];
    float* out = (float*)d_out;

    // Per-step fp8 residual scales: field magnitude ~2^(i-7) after i steps,
    // residual ~2^-11 of that -> scale 2^(18-i) centers it in e4m3 range.
    float S[8];
    for (int i = 0; i < 8; i++) S[i] = ldexpf(1.0f, 18 - i);

    // ddf0 (i=0) into A.
    k_scale_pad<<<NBLOCKS, NTHREADS>>>(dvf, S[0]);

    // 7 squaring steps, ping-pong A<->B; final step writes float3 to d_out.
    k_step<true,  false><<<NBLOCKS, NTHREADS>>>(nullptr, 1.0f / S[0], S[1]); // A->B
    k_step<false, false><<<NBLOCKS, NTHREADS>>>(nullptr, 1.0f / S[1], S[2]); // B->A
    k_step<true,  false><<<NBLOCKS, NTHREADS>>>(nullptr, 1.0f / S[2], S[3]); // A->B
    k_step<false, false><<<NBLOCKS, NTHREADS>>>(nullptr, 1.0f / S[3], S[4]); // B->A
    k_step<true,  false><<<NBLOCKS, NTHREADS>>>(nullptr, 1.0f / S[4], S[5]); // A->B
    k_step<false, false><<<NBLOCKS, NTHREADS>>>(nullptr, 1.0f / S[5], S[6]); // B->A
    k_step<true,  true ><<<NBLOCKS, NTHREADS>>>(out, 1.0f / S[6], 0.0f);     // A->out
}